// round 4
// baseline (speedup 1.0000x reference)
#include <cuda_runtime.h>

#define BB 8
#define TT 512
#define CC 128
#define HH 1024
#define GBLK 148
#define GW 7

// ---------------- static scratch ----------------
__device__ float g_xg[BB * TT * 3 * HH];
__device__ float g_h[2][BB * HH];
__device__ float g_emb2[BB * CC * TT * 8];
__device__ float g_x3[BB * CC * TT * 8];
__device__ float g_e3x[BB * CC * TT * 16];
__device__ float g_x2[BB * CC * TT * 16];
__device__ float g_e2x[BB * CC * TT * 32];
__device__ float g_x1[BB * CC * TT * 32];
__device__ float g_e1x[BB * CC * TT * 64];
__device__ float g_wtT3[3 * CC * CC];
__device__ float g_wtT2[3 * CC * CC];
__device__ float g_wtT1[3 * CC * CC];
__device__ unsigned g_mtile_done[32];
__device__ unsigned g_bar_count;
__device__ unsigned g_bar_gen;

__global__ void k_init()
{
    if (threadIdx.x < 32) g_mtile_done[threadIdx.x] = 0;
}

// ---------------- grid barrier (all blocks resident) ----------------
__device__ __forceinline__ void grid_barrier()
{
    __syncthreads();
    if (threadIdx.x == 0) {
        volatile unsigned* genp = &g_bar_gen;
        unsigned g = *genp;
        __threadfence();
        if (atomicAdd(&g_bar_count, 1u) == gridDim.x - 1) {
            g_bar_count = 0;
            __threadfence();
            atomicAdd(&g_bar_gen, 1u);
        } else {
            while (*genp == g) { __nanosleep(32); }
        }
        __threadfence();
    }
    __syncthreads();
}

// ---------------- xg = emb @ Wih^T + bih : 128x128 tile SGEMM ----------------
// blockIdx.y remapped phase-major so tiles for GRU steps 0..127 finish first.
__global__ __launch_bounds__(256, 2) void k_xg(const float* __restrict__ A,
                                               const float* __restrict__ W,
                                               const float* __restrict__ bias)
{
    __shared__ __align__(16) float As[16][128];
    __shared__ __align__(16) float Bs[16][128];
    int tid = threadIdx.x;
    int tx = tid & 15, ty = tid >> 4;
    int mtile = ((blockIdx.y & 7) << 2) | (blockIdx.y >> 3);
    int m0 = mtile * 128, n0 = blockIdx.x * 128;
    float acc[8][8];
#pragma unroll
    for (int r = 0; r < 8; ++r)
#pragma unroll
        for (int q = 0; q < 8; ++q) acc[r][q] = 0.f;

    for (int kb = 0; kb < HH; kb += 16) {
#pragma unroll
        for (int i = 0; i < 2; ++i) {
            int e4 = tid + i * 256;
            int mm = e4 >> 2, k4 = (e4 & 3) << 2;
            float4 v = *(const float4*)&A[(size_t)(m0 + mm) * HH + kb + k4];
            As[k4 + 0][mm] = v.x; As[k4 + 1][mm] = v.y;
            As[k4 + 2][mm] = v.z; As[k4 + 3][mm] = v.w;
        }
#pragma unroll
        for (int i = 0; i < 2; ++i) {
            int e4 = tid + i * 256;
            int nn = e4 >> 2, k4 = (e4 & 3) << 2;
            float4 v = *(const float4*)&W[(size_t)(n0 + nn) * HH + kb + k4];
            Bs[k4 + 0][nn] = v.x; Bs[k4 + 1][nn] = v.y;
            Bs[k4 + 2][nn] = v.z; Bs[k4 + 3][nn] = v.w;
        }
        __syncthreads();
#pragma unroll
        for (int kk = 0; kk < 16; ++kk) {
            float4 a0 = *(const float4*)&As[kk][ty * 8];
            float4 a1 = *(const float4*)&As[kk][ty * 8 + 4];
            float4 b0 = *(const float4*)&Bs[kk][tx * 8];
            float4 b1 = *(const float4*)&Bs[kk][tx * 8 + 4];
            float a[8] = { a0.x, a0.y, a0.z, a0.w, a1.x, a1.y, a1.z, a1.w };
            float b[8] = { b0.x, b0.y, b0.z, b0.w, b1.x, b1.y, b1.z, b1.w };
#pragma unroll
            for (int r = 0; r < 8; ++r)
#pragma unroll
                for (int q = 0; q < 8; ++q)
                    acc[r][q] = fmaf(a[r], b[q], acc[r][q]);
        }
        __syncthreads();
    }
#pragma unroll
    for (int r = 0; r < 8; ++r) {
        int m = m0 + ty * 8 + r;
#pragma unroll
        for (int h = 0; h < 2; ++h) {
            int n = n0 + tx * 8 + h * 4;
            float4 o;
            o.x = acc[r][h * 4 + 0] + bias[n + 0];
            o.y = acc[r][h * 4 + 1] + bias[n + 1];
            o.z = acc[r][h * 4 + 2] + bias[n + 2];
            o.w = acc[r][h * 4 + 3] + bias[n + 3];
            *(float4*)&g_xg[(size_t)m * (3 * HH) + n] = o;
        }
    }
    __threadfence();
    __syncthreads();
    if (tid == 0) atomicAdd(&g_mtile_done[mtile], 1u);
}

// ---------------- persistent GRU: 148 blocks x 224 thr, reg-resident Whh ------
__global__ __launch_bounds__(224, 2) void k_gru(const float* __restrict__ h0,
                                                const float* __restrict__ Whh,
                                                const float* __restrict__ bhh,
                                                float* __restrict__ outHT)
{
    __shared__ __align__(16) float hs[BB][HH];
    int tid = threadIdx.x;
    int lane = tid & 31, wid = tid >> 5;
    int j = blockIdx.x * GW + wid;
    bool valid = (j < HH);
    int c = j & 127, f = j >> 7;

    float4 wr4[8], wz4[8], wn4[8];
    float br = 0.f, bz = 0.f, bn = 0.f;
    if (valid) {
        const float* wr = Whh + (size_t)j * HH;
        const float* wz = Whh + (size_t)(j + HH) * HH;
        const float* wn = Whh + (size_t)(j + 2 * HH) * HH;
#pragma unroll
        for (int i = 0; i < 8; ++i) {
            wr4[i] = *(const float4*)&wr[i * 128 + lane * 4];
            wz4[i] = *(const float4*)&wz[i * 128 + lane * 4];
            wn4[i] = *(const float4*)&wn[i * 128 + lane * 4];
        }
        br = bhh[j]; bz = bhh[j + HH]; bn = bhh[j + 2 * HH];
    } else {
#pragma unroll
        for (int i = 0; i < 8; ++i) {
            wr4[i] = make_float4(0, 0, 0, 0);
            wz4[i] = make_float4(0, 0, 0, 0);
            wn4[i] = make_float4(0, 0, 0, 0);
        }
    }

    {
        int i = blockIdx.x * 224 + tid;
        if (i < BB * HH) g_h[0][i] = h0[i];
    }
    grid_barrier();

    for (int t = 0; t < TT; ++t) {
        // gate on xg producer once per 128-step phase
        if ((t & 127) == 0) {
            if (tid == 0) {
                int phase = t >> 7;
#pragma unroll
                for (int b = 0; b < 8; ++b) {
                    volatile unsigned* p = &g_mtile_done[b * 4 + phase];
                    while (*p < 24u) { __nanosleep(128); }
                }
                __threadfence();
            }
            __syncthreads();
        }

        const float4* hp = (const float4*)&g_h[t & 1][0];
        float* hw = &g_h[(t + 1) & 1][0];
#pragma unroll
        for (int i = 0; i < 10; ++i) {
            int idx4 = tid + i * 224;
            if (idx4 < 2048) {
                float4 v = hp[idx4];
                *(float4*)&hs[idx4 >> 8][(idx4 & 255) * 4] = v;
            }
        }
        __syncthreads();

        float xr = 0.f, xz = 0.f, xn = 0.f;
        if (valid && lane < 8) {
            const float* xgp = g_xg + (size_t)(lane * TT + t) * (3 * HH);
            xr = xgp[j]; xz = xgp[j + HH]; xn = xgp[j + 2 * HH];
        }

        float accR[8], accZ[8], accN[8];
#pragma unroll
        for (int b = 0; b < 8; ++b) { accR[b] = 0.f; accZ[b] = 0.f; accN[b] = 0.f; }

        if (valid) {
#pragma unroll
            for (int i = 0; i < 8; ++i) {
                float4 a = wr4[i], b4 = wz4[i], c4 = wn4[i];
#pragma unroll
                for (int b = 0; b < 8; ++b) {
                    float4 h4 = *(const float4*)&hs[b][i * 128 + lane * 4];
                    accR[b] = fmaf(a.x, h4.x, accR[b]);
                    accR[b] = fmaf(a.y, h4.y, accR[b]);
                    accR[b] = fmaf(a.z, h4.z, accR[b]);
                    accR[b] = fmaf(a.w, h4.w, accR[b]);
                    accZ[b] = fmaf(b4.x, h4.x, accZ[b]);
                    accZ[b] = fmaf(b4.y, h4.y, accZ[b]);
                    accZ[b] = fmaf(b4.z, h4.z, accZ[b]);
                    accZ[b] = fmaf(b4.w, h4.w, accZ[b]);
                    accN[b] = fmaf(c4.x, h4.x, accN[b]);
                    accN[b] = fmaf(c4.y, h4.y, accN[b]);
                    accN[b] = fmaf(c4.z, h4.z, accN[b]);
                    accN[b] = fmaf(c4.w, h4.w, accN[b]);
                }
            }
#pragma unroll
            for (int b = 0; b < 8; ++b)
#pragma unroll
                for (int off = 16; off; off >>= 1) {
                    accR[b] += __shfl_xor_sync(0xffffffffu, accR[b], off);
                    accZ[b] += __shfl_xor_sync(0xffffffffu, accZ[b], off);
                    accN[b] += __shfl_xor_sync(0xffffffffu, accN[b], off);
                }
            if (lane < 8) {
                int b = lane;
                float r = 1.f / (1.f + __expf(-(xr + accR[b] + br)));
                float z = 1.f / (1.f + __expf(-(xz + accZ[b] + bz)));
                float n = tanhf(xn + r * (accN[b] + bn));
                float hnew = (1.f - z) * n + z * hs[b][j];
                hw[b * HH + j] = hnew;
                g_emb2[((size_t)(b * CC + c) * TT + t) * 8 + f] = hnew;
                if (t == TT - 1) outHT[b * HH + j] = hnew;
            }
        }
        grid_barrier();
    }
}

// ---------------- 1x1 conv over channels + bias + skip ----------------
__global__ __launch_bounds__(256) void k_pconv(float* __restrict__ out,
                                               const float* __restrict__ in,
                                               const float* __restrict__ W,
                                               const float* __restrict__ bias,
                                               const float* __restrict__ skip,
                                               int TF)
{
    __shared__ __align__(16) float Xs[128][64];
    __shared__ __align__(16) float Ws[16][128];
    int tid = threadIdx.x;
    int tx = tid & 15, ty = tid >> 4;
    int b = blockIdx.y;
    int p0 = blockIdx.x * 64;

#pragma unroll
    for (int i = 0; i < 8; ++i) {
        int e4 = tid + i * 256;
        int ch = e4 >> 4, pq = (e4 & 15) << 2;
        *(float4*)&Xs[ch][pq] = *(const float4*)&in[(size_t)(b * CC + ch) * TF + p0 + pq];
    }
    float acc[8][4];
#pragma unroll
    for (int r = 0; r < 8; ++r)
#pragma unroll
        for (int q = 0; q < 4; ++q) acc[r][q] = 0.f;

    for (int kb = 0; kb < CC; kb += 16) {
#pragma unroll
        for (int i = 0; i < 2; ++i) {
            int e4 = tid * 2 + i;
            int oc = e4 >> 2, k4 = (e4 & 3) << 2;
            float4 v = *(const float4*)&W[oc * CC + kb + k4];
            Ws[k4 + 0][oc] = v.x; Ws[k4 + 1][oc] = v.y;
            Ws[k4 + 2][oc] = v.z; Ws[k4 + 3][oc] = v.w;
        }
        __syncthreads();
#pragma unroll
        for (int kk = 0; kk < 16; ++kk) {
            float4 xv = *(const float4*)&Xs[kb + kk][tx * 4];
            float w[8];
#pragma unroll
            for (int r = 0; r < 8; ++r) w[r] = Ws[kk][ty * 8 + r];
#pragma unroll
            for (int r = 0; r < 8; ++r) {
                acc[r][0] = fmaf(w[r], xv.x, acc[r][0]);
                acc[r][1] = fmaf(w[r], xv.y, acc[r][1]);
                acc[r][2] = fmaf(w[r], xv.z, acc[r][2]);
                acc[r][3] = fmaf(w[r], xv.w, acc[r][3]);
            }
        }
        __syncthreads();
    }
#pragma unroll
    for (int r = 0; r < 8; ++r) {
        int oc = ty * 8 + r;
        size_t idx = (size_t)(b * CC + oc) * TF + p0 + tx * 4;
        float bv = bias[oc];
        float4 s = *(const float4*)&skip[idx];
        float4 o;
        o.x = acc[r][0] + bv + s.x; o.y = acc[r][1] + bv + s.y;
        o.z = acc[r][2] + bv + s.z; o.w = acc[r][3] + bv + s.w;
        *(float4*)&out[idx] = o;
    }
}

// ---------------- weight transpose for convt: (oc,ic,tap) -> [tap][ic][oc] ----
__global__ __launch_bounds__(256) void k_wtT(const float* __restrict__ src,
                                             float* __restrict__ dst)
{
    int i = blockIdx.x * 256 + threadIdx.x;
    if (i < 3 * CC * CC) {
        int oc = i & 127, ic = (i >> 7) & 127, tap = i >> 14;
        dst[i] = src[(oc * CC + ic) * 3 + tap];
    }
}

// ---------------- transposed conv over freq (k=3,s=2) + ReLU ----------------
__global__ __launch_bounds__(128) void k_convt(float* __restrict__ out,
                                               const float* __restrict__ in,
                                               const float* __restrict__ wT,
                                               const float* __restrict__ bias,
                                               int Fin, int TF)
{
    __shared__ __align__(16) float Xs[128][36];
    __shared__ __align__(16) float Ws[3][16][128];
    int tid = threadIdx.x;
    int tx = tid & 7, ty = tid >> 3;
    int b = blockIdx.y;
    int p0 = blockIdx.x * 32;

#pragma unroll
    for (int i = 0; i < 8; ++i) {
        int e4 = tid + i * 128;
        int ch = e4 >> 3, pq = (e4 & 7) << 2;
        *(float4*)&Xs[ch][pq] = *(const float4*)&in[(size_t)(b * CC + ch) * TF + p0 + pq];
    }
    int p_ = tx * 4;
    bool sh[4];
#pragma unroll
    for (int jj = 0; jj < 4; ++jj) sh[jj] = (((p_ + jj) & (Fin - 1)) != Fin - 1);

    float ae[8][4], ao[8][4];
#pragma unroll
    for (int r = 0; r < 8; ++r)
#pragma unroll
        for (int q = 0; q < 4; ++q) { ae[r][q] = 0.f; ao[r][q] = 0.f; }

    for (int kb = 0; kb < CC; kb += 16) {
        __syncthreads();
#pragma unroll
        for (int i = 0; i < 12; ++i) {
            int idx = tid + i * 128;
            int tap = idx / 512, rem = idx & 511;
            int kkk = rem >> 5, oc4 = (rem & 31) << 2;
            *(float4*)&Ws[tap][kkk][oc4] =
                *(const float4*)&wT[(tap * CC + kb + kkk) * CC + oc4];
        }
        __syncthreads();
#pragma unroll
        for (int kk = 0; kk < 16; ++kk) {
            const float* xrow = &Xs[kb + kk][0];
            float4 xv = *(const float4*)&xrow[p_];
            float xnext = xrow[p_ + 4];
            float x[4] = { xv.x, xv.y, xv.z, xv.w };
            float xs[4];
            xs[0] = sh[0] ? xv.y : 0.f;
            xs[1] = sh[1] ? xv.z : 0.f;
            xs[2] = sh[2] ? xv.w : 0.f;
            xs[3] = sh[3] ? xnext : 0.f;
            float4 w0a = *(const float4*)&Ws[0][kk][ty * 8];
            float4 w0b = *(const float4*)&Ws[0][kk][ty * 8 + 4];
            float4 w1a = *(const float4*)&Ws[1][kk][ty * 8];
            float4 w1b = *(const float4*)&Ws[1][kk][ty * 8 + 4];
            float4 w2a = *(const float4*)&Ws[2][kk][ty * 8];
            float4 w2b = *(const float4*)&Ws[2][kk][ty * 8 + 4];
            float w0[8] = { w0a.x, w0a.y, w0a.z, w0a.w, w0b.x, w0b.y, w0b.z, w0b.w };
            float w1[8] = { w1a.x, w1a.y, w1a.z, w1a.w, w1b.x, w1b.y, w1b.z, w1b.w };
            float w2[8] = { w2a.x, w2a.y, w2a.z, w2a.w, w2b.x, w2b.y, w2b.z, w2b.w };
#pragma unroll
            for (int r = 0; r < 8; ++r)
#pragma unroll
                for (int jj = 0; jj < 4; ++jj) {
                    ae[r][jj] = fmaf(w1[r], x[jj], ae[r][jj]);
                    ao[r][jj] = fmaf(w0[r], x[jj], ao[r][jj]);
                    ao[r][jj] = fmaf(w2[r], xs[jj], ao[r][jj]);
                }
        }
    }
    int TF2 = TF * 2;
#pragma unroll
    for (int r = 0; r < 8; ++r) {
        int oc = ty * 8 + r;
        float bv = bias[oc];
#pragma unroll
        for (int jj = 0; jj < 4; ++jj) {
            int p = p0 + p_ + jj;
            float2 o;
            o.x = fmaxf(ae[r][jj] + bv, 0.f);
            o.y = fmaxf(ao[r][jj] + bv, 0.f);
            *(float2*)&out[(size_t)(b * CC + oc) * TF2 + 2 * p] = o;
        }
    }
}

// ---------------- final: pre = w0p@e0 + b0p + e1x ; m = sigmoid(conv3(pre)) ----
__global__ __launch_bounds__(256) void k_final(const float* __restrict__ e0,
                                               const float* __restrict__ W,
                                               const float* __restrict__ bias,
                                               const float* __restrict__ w0o,
                                               const float* __restrict__ b0o,
                                               float* __restrict__ outm)
{
    __shared__ __align__(16) float Xs[128][64];
    __shared__ __align__(16) float Ws[16][128];
    __shared__ float wo[128][3];
    const int TF = TT * 64;
    int tid = threadIdx.x;
    int tx = tid & 15, ty = tid >> 4;
    int b = blockIdx.y, t = blockIdx.x;
    int p0 = t * 64;

#pragma unroll
    for (int i = 0; i < 8; ++i) {
        int e4 = tid + i * 256;
        int ch = e4 >> 4, pq = (e4 & 15) << 2;
        *(float4*)&Xs[ch][pq] = *(const float4*)&e0[(size_t)(b * CC + ch) * TF + p0 + pq];
    }
    for (int i = tid; i < 384; i += 256) wo[i / 3][i % 3] = w0o[i];

    float acc[8][4];
#pragma unroll
    for (int r = 0; r < 8; ++r)
#pragma unroll
        for (int q = 0; q < 4; ++q) acc[r][q] = 0.f;

    for (int kb = 0; kb < CC; kb += 16) {
#pragma unroll
        for (int i = 0; i < 2; ++i) {
            int e4 = tid * 2 + i;
            int oc = e4 >> 2, k4 = (e4 & 3) << 2;
            float4 v = *(const float4*)&W[oc * CC + kb + k4];
            Ws[k4 + 0][oc] = v.x; Ws[k4 + 1][oc] = v.y;
            Ws[k4 + 2][oc] = v.z; Ws[k4 + 3][oc] = v.w;
        }
        __syncthreads();
#pragma unroll
        for (int kk = 0; kk < 16; ++kk) {
            float4 xv = *(const float4*)&Xs[kb + kk][tx * 4];
            float w[8];
#pragma unroll
            for (int r = 0; r < 8; ++r) w[r] = Ws[kk][ty * 8 + r];
#pragma unroll
            for (int r = 0; r < 8; ++r) {
                acc[r][0] = fmaf(w[r], xv.x, acc[r][0]);
                acc[r][1] = fmaf(w[r], xv.y, acc[r][1]);
                acc[r][2] = fmaf(w[r], xv.z, acc[r][2]);
                acc[r][3] = fmaf(w[r], xv.w, acc[r][3]);
            }
        }
        __syncthreads();
    }
#pragma unroll
    for (int r = 0; r < 8; ++r) {
        int oc = ty * 8 + r;
        float bv = bias[oc];
#pragma unroll
        for (int jj = 0; jj < 4; ++jj) {
            int p = tx * 4 + jj;
            Xs[oc][p] = acc[r][jj] + bv +
                g_e1x[(size_t)(b * CC + oc) * TF + p0 + p];
        }
    }
    __syncthreads();
    int f = tid >> 2, q = tid & 3;
    float s = 0.f;
#pragma unroll 4
    for (int i = 0; i < 32; ++i) {
        int ch = q * 32 + i;
        float x0 = Xs[ch][f];
        float xm = (f > 0) ? Xs[ch][f - 1] : 0.f;
        float xp = (f < 63) ? Xs[ch][f + 1] : 0.f;
        s = fmaf(wo[ch][0], xm, s);
        s = fmaf(wo[ch][1], x0, s);
        s = fmaf(wo[ch][2], xp, s);
    }
    s += __shfl_down_sync(0xffffffffu, s, 1);
    s += __shfl_down_sync(0xffffffffu, s, 2);
    if (q == 0) outm[((size_t)b * TT + t) * 64 + f] = 1.f / (1.f + __expf(-(s + b0o[0])));
}

// ---------------------------------- launch ----------------------------------
extern "C" void kernel_launch(void* const* d_in, const int* in_sizes, int n_in,
                              void* d_out, int out_size)
{
    const float* emb   = (const float*)d_in[0];
    const float* e3    = (const float*)d_in[1];
    const float* e2    = (const float*)d_in[2];
    const float* e1    = (const float*)d_in[3];
    const float* e0    = (const float*)d_in[4];
    const float* h_erb = (const float*)d_in[5];
    const float* Wih   = (const float*)d_in[6];
    const float* Whh   = (const float*)d_in[7];
    const float* bih   = (const float*)d_in[8];
    const float* bhh   = (const float*)d_in[9];
    const float* w3p   = (const float*)d_in[10];
    const float* b3p   = (const float*)d_in[11];
    const float* w2p   = (const float*)d_in[12];
    const float* b2p   = (const float*)d_in[13];
    const float* w1p   = (const float*)d_in[14];
    const float* b1p   = (const float*)d_in[15];
    const float* w0p   = (const float*)d_in[16];
    const float* b0p   = (const float*)d_in[17];
    const float* wt3   = (const float*)d_in[18];
    const float* bt3   = (const float*)d_in[19];
    const float* wt2   = (const float*)d_in[20];
    const float* bt2   = (const float*)d_in[21];
    const float* wt1   = (const float*)d_in[22];
    const float* bt1   = (const float*)d_in[23];
    const float* w0o   = (const float*)d_in[24];
    const float* b0o   = (const float*)d_in[25];
    float* out = (float*)d_out;

    float* gx3;  cudaGetSymbolAddress((void**)&gx3,  g_x3);
    float* ge3x; cudaGetSymbolAddress((void**)&ge3x, g_e3x);
    float* gx2;  cudaGetSymbolAddress((void**)&gx2,  g_x2);
    float* ge2x; cudaGetSymbolAddress((void**)&ge2x, g_e2x);
    float* gx1;  cudaGetSymbolAddress((void**)&gx1,  g_x1);
    float* ge1x; cudaGetSymbolAddress((void**)&ge1x, g_e1x);
    float* gemb2;cudaGetSymbolAddress((void**)&gemb2,g_emb2);
    float* gw3;  cudaGetSymbolAddress((void**)&gw3,  g_wtT3);
    float* gw2;  cudaGetSymbolAddress((void**)&gw2,  g_wtT2);
    float* gw1;  cudaGetSymbolAddress((void**)&gw1,  g_wtT1);

    static cudaStream_t s2 = nullptr;
    static cudaEvent_t evA = nullptr, evB = nullptr;
    if (s2 == nullptr) {
        cudaStreamCreateWithFlags(&s2, cudaStreamNonBlocking);
        cudaEventCreateWithFlags(&evA, cudaEventDisableTiming);
        cudaEventCreateWithFlags(&evB, cudaEventDisableTiming);
    }

    // reset producer counters, then fork side stream
    k_init<<<1, 32>>>();
    cudaEventRecord(evA, 0);
    cudaStreamWaitEvent(s2, evA, 0);

    // side stream: xg GEMM (phase-ordered) + weight transposes
    k_xg<<<dim3(24, 32), 256, 0, s2>>>(emb, Wih, bih);
    k_wtT<<<192, 256, 0, s2>>>(wt3, gw3);
    k_wtT<<<192, 256, 0, s2>>>(wt2, gw2);
    k_wtT<<<192, 256, 0, s2>>>(wt1, gw1);
    cudaEventRecord(evB, s2);

    // main stream: persistent GRU runs concurrently, self-synchronizes on xg tiles
    k_gru<<<GBLK, 224>>>(h_erb, Whh, bhh, out + BB * TT * 64);

    // join side stream before decoder
    cudaStreamWaitEvent(0, evB, 0);

    k_pconv<<<dim3(64, 8),  256>>>(gx3, e3, w3p, b3p, gemb2, TT * 8);
    k_convt<<<dim3(128, 8), 128>>>(ge3x, gx3, gw3, bt3, 8, TT * 8);

    k_pconv<<<dim3(128, 8), 256>>>(gx2, e2, w2p, b2p, ge3x, TT * 16);
    k_convt<<<dim3(256, 8), 128>>>(ge2x, gx2, gw2, bt2, 16, TT * 16);

    k_pconv<<<dim3(256, 8), 256>>>(gx1, e1, w1p, b1p, ge2x, TT * 32);
    k_convt<<<dim3(512, 8), 128>>>(ge1x, gx1, gw1, bt1, 32, TT * 32);

    k_final<<<dim3(512, 8), 256>>>(e0, w0p, b0p, w0o, b0o, out);
}

// round 5
// speedup vs baseline: 1.3588x; 1.3588x over previous
#include <cuda_runtime.h>

#define BB 8
#define TT 512
#define CC 128
#define HH 1024
#define GBLK 148
#define GW 7

typedef unsigned long long ull;

// ---------------- f32x2 helpers ----------------
__device__ __forceinline__ ull dup2(float x)
{
    ull r;
    asm("mov.b64 %0, {%1, %1};" : "=l"(r) : "f"(x));
    return r;
}
__device__ __forceinline__ ull ffma2(ull a, ull b, ull c)
{
    ull d;
    asm("fma.rn.f32x2 %0, %1, %2, %3;" : "=l"(d) : "l"(a), "l"(b), "l"(c));
    return d;
}
__device__ __forceinline__ float2 unpk2(ull v)
{
    float2 f;
    asm("mov.b64 {%0, %1}, %2;" : "=f"(f.x), "=f"(f.y) : "l"(v));
    return f;
}

// ---------------- static scratch ----------------
__device__ float g_xg[BB * TT * 3 * HH];
__device__ float g_h[2][BB * HH];
__device__ float g_emb2[BB * CC * TT * 8];
__device__ float g_x3[BB * CC * TT * 8];
__device__ float g_e3x[BB * CC * TT * 16];
__device__ float g_x2[BB * CC * TT * 16];
__device__ float g_e2x[BB * CC * TT * 32];
__device__ float g_x1[BB * CC * TT * 32];
__device__ float g_e1x[BB * CC * TT * 64];
__device__ float g_wtT[3 * CC * CC];
__device__ unsigned g_bar_count;
__device__ unsigned g_bar_gen;

// ---------------- grid barrier (all blocks resident) ----------------
__device__ __forceinline__ void grid_barrier()
{
    __syncthreads();
    if (threadIdx.x == 0) {
        volatile unsigned* genp = &g_bar_gen;
        unsigned g = *genp;
        __threadfence();
        if (atomicAdd(&g_bar_count, 1u) == gridDim.x - 1) {
            g_bar_count = 0;
            __threadfence();
            atomicAdd(&g_bar_gen, 1u);
        } else {
            while (*genp == g) { __nanosleep(32); }
        }
        __threadfence();
    }
    __syncthreads();
}

// ---------------- xg = emb @ Wih^T + bih : 128x128 tile, f32x2 ----------------
__global__ __launch_bounds__(256) void k_xg(const float* __restrict__ A,
                                            const float* __restrict__ W,
                                            const float* __restrict__ bias)
{
    __shared__ __align__(16) float As[16][128];
    __shared__ __align__(16) float Bs[16][128];
    int tid = threadIdx.x;
    int tx = tid & 15, ty = tid >> 4;
    int m0 = blockIdx.y * 128, n0 = blockIdx.x * 128;
    ull acc2[8][4];
#pragma unroll
    for (int r = 0; r < 8; ++r)
#pragma unroll
        for (int q = 0; q < 4; ++q) acc2[r][q] = 0ull;

    for (int kb = 0; kb < HH; kb += 16) {
#pragma unroll
        for (int i = 0; i < 2; ++i) {
            int e4 = tid + i * 256;
            int mm = e4 >> 2, k4 = (e4 & 3) << 2;
            float4 v = *(const float4*)&A[(size_t)(m0 + mm) * HH + kb + k4];
            As[k4 + 0][mm] = v.x; As[k4 + 1][mm] = v.y;
            As[k4 + 2][mm] = v.z; As[k4 + 3][mm] = v.w;
        }
#pragma unroll
        for (int i = 0; i < 2; ++i) {
            int e4 = tid + i * 256;
            int nn = e4 >> 2, k4 = (e4 & 3) << 2;
            float4 v = *(const float4*)&W[(size_t)(n0 + nn) * HH + kb + k4];
            Bs[k4 + 0][nn] = v.x; Bs[k4 + 1][nn] = v.y;
            Bs[k4 + 2][nn] = v.z; Bs[k4 + 3][nn] = v.w;
        }
        __syncthreads();
#pragma unroll
        for (int kk = 0; kk < 16; ++kk) {
            float4 a0 = *(const float4*)&As[kk][ty * 8];
            float4 a1 = *(const float4*)&As[kk][ty * 8 + 4];
            ull da[8];
            da[0] = dup2(a0.x); da[1] = dup2(a0.y);
            da[2] = dup2(a0.z); da[3] = dup2(a0.w);
            da[4] = dup2(a1.x); da[5] = dup2(a1.y);
            da[6] = dup2(a1.z); da[7] = dup2(a1.w);
            ull wb[4];
#pragma unroll
            for (int q = 0; q < 4; ++q)
                wb[q] = *(const ull*)&Bs[kk][tx * 8 + 2 * q];
#pragma unroll
            for (int r = 0; r < 8; ++r)
#pragma unroll
                for (int q = 0; q < 4; ++q)
                    acc2[r][q] = ffma2(wb[q], da[r], acc2[r][q]);
        }
        __syncthreads();
    }
#pragma unroll
    for (int r = 0; r < 8; ++r) {
        int m = m0 + ty * 8 + r;
        int n = n0 + tx * 8;
        float2 p0 = unpk2(acc2[r][0]), p1 = unpk2(acc2[r][1]);
        float2 p2 = unpk2(acc2[r][2]), p3 = unpk2(acc2[r][3]);
        float4 o0, o1;
        o0.x = p0.x + bias[n + 0]; o0.y = p0.y + bias[n + 1];
        o0.z = p1.x + bias[n + 2]; o0.w = p1.y + bias[n + 3];
        o1.x = p2.x + bias[n + 4]; o1.y = p2.y + bias[n + 5];
        o1.z = p3.x + bias[n + 6]; o1.w = p3.y + bias[n + 7];
        *(float4*)&g_xg[(size_t)m * (3 * HH) + n] = o0;
        *(float4*)&g_xg[(size_t)m * (3 * HH) + n + 4] = o1;
    }
}

// ---------------- persistent GRU: 148 blocks x 224 thr, reg-resident Whh ------
__global__ __launch_bounds__(224) void k_gru(const float* __restrict__ h0,
                                             const float* __restrict__ Whh,
                                             const float* __restrict__ bhh,
                                             float* __restrict__ outHT)
{
    __shared__ __align__(16) float hs[BB][HH];
    int tid = threadIdx.x;
    int lane = tid & 31, wid = tid >> 5;
    int j = blockIdx.x * GW + wid;
    bool valid = (j < HH);
    int c = j & 127, f = j >> 7;

    float4 wr4[8], wz4[8], wn4[8];
    float br = 0.f, bz = 0.f, bn = 0.f;
    if (valid) {
        const float* wr = Whh + (size_t)j * HH;
        const float* wz = Whh + (size_t)(j + HH) * HH;
        const float* wn = Whh + (size_t)(j + 2 * HH) * HH;
#pragma unroll
        for (int i = 0; i < 8; ++i) {
            wr4[i] = *(const float4*)&wr[i * 128 + lane * 4];
            wz4[i] = *(const float4*)&wz[i * 128 + lane * 4];
            wn4[i] = *(const float4*)&wn[i * 128 + lane * 4];
        }
        br = bhh[j]; bz = bhh[j + HH]; bn = bhh[j + 2 * HH];
    } else {
#pragma unroll
        for (int i = 0; i < 8; ++i) {
            wr4[i] = make_float4(0, 0, 0, 0);
            wz4[i] = make_float4(0, 0, 0, 0);
            wn4[i] = make_float4(0, 0, 0, 0);
        }
    }

    {
        int i = blockIdx.x * 224 + tid;
        if (i < BB * HH) g_h[0][i] = h0[i];
    }
    grid_barrier();

    for (int t = 0; t < TT; ++t) {
        const float4* hp = (const float4*)&g_h[t & 1][0];
        float* hw = &g_h[(t + 1) & 1][0];
#pragma unroll
        for (int i = 0; i < 10; ++i) {
            int idx4 = tid + i * 224;
            if (idx4 < 2048) {
                float4 v = hp[idx4];
                *(float4*)&hs[idx4 >> 8][(idx4 & 255) * 4] = v;
            }
        }
        __syncthreads();

        float xr = 0.f, xz = 0.f, xn = 0.f;
        if (valid && lane < 8) {
            const float* xgp = g_xg + (size_t)(lane * TT + t) * (3 * HH);
            xr = xgp[j]; xz = xgp[j + HH]; xn = xgp[j + 2 * HH];
        }

        float accR[8], accZ[8], accN[8];
#pragma unroll
        for (int b = 0; b < 8; ++b) { accR[b] = 0.f; accZ[b] = 0.f; accN[b] = 0.f; }

        if (valid) {
#pragma unroll
            for (int i = 0; i < 8; ++i) {
                float4 a = wr4[i], b4 = wz4[i], c4 = wn4[i];
#pragma unroll
                for (int b = 0; b < 8; ++b) {
                    float4 h4 = *(const float4*)&hs[b][i * 128 + lane * 4];
                    accR[b] = fmaf(a.x, h4.x, accR[b]);
                    accR[b] = fmaf(a.y, h4.y, accR[b]);
                    accR[b] = fmaf(a.z, h4.z, accR[b]);
                    accR[b] = fmaf(a.w, h4.w, accR[b]);
                    accZ[b] = fmaf(b4.x, h4.x, accZ[b]);
                    accZ[b] = fmaf(b4.y, h4.y, accZ[b]);
                    accZ[b] = fmaf(b4.z, h4.z, accZ[b]);
                    accZ[b] = fmaf(b4.w, h4.w, accZ[b]);
                    accN[b] = fmaf(c4.x, h4.x, accN[b]);
                    accN[b] = fmaf(c4.y, h4.y, accN[b]);
                    accN[b] = fmaf(c4.z, h4.z, accN[b]);
                    accN[b] = fmaf(c4.w, h4.w, accN[b]);
                }
            }
#pragma unroll
            for (int b = 0; b < 8; ++b)
#pragma unroll
                for (int off = 16; off; off >>= 1) {
                    accR[b] += __shfl_xor_sync(0xffffffffu, accR[b], off);
                    accZ[b] += __shfl_xor_sync(0xffffffffu, accZ[b], off);
                    accN[b] += __shfl_xor_sync(0xffffffffu, accN[b], off);
                }
            if (lane < 8) {
                int b = lane;
                float r = 1.f / (1.f + __expf(-(xr + accR[b] + br)));
                float z = 1.f / (1.f + __expf(-(xz + accZ[b] + bz)));
                float n = tanhf(xn + r * (accN[b] + bn));
                float hnew = (1.f - z) * n + z * hs[b][j];
                hw[b * HH + j] = hnew;
                g_emb2[((size_t)(b * CC + c) * TT + t) * 8 + f] = hnew;
                if (t == TT - 1) outHT[b * HH + j] = hnew;
            }
        }
        grid_barrier();
    }
}

// ---------------- 1x1 conv over channels + bias + skip, f32x2 ----------------
__global__ __launch_bounds__(256) void k_pconv(float* __restrict__ out,
                                               const float* __restrict__ in,
                                               const float* __restrict__ W,
                                               const float* __restrict__ bias,
                                               const float* __restrict__ skip,
                                               int TF)
{
    __shared__ __align__(16) float Xs[128][64];
    __shared__ __align__(16) float Ws[16][128];
    int tid = threadIdx.x;
    int tx = tid & 15, ty = tid >> 4;
    int b = blockIdx.y;
    int p0 = blockIdx.x * 64;

#pragma unroll
    for (int i = 0; i < 8; ++i) {
        int e4 = tid + i * 256;
        int ch = e4 >> 4, pq = (e4 & 15) << 2;
        *(float4*)&Xs[ch][pq] = *(const float4*)&in[(size_t)(b * CC + ch) * TF + p0 + pq];
    }
    ull acc2[4][4];
#pragma unroll
    for (int p = 0; p < 4; ++p)
#pragma unroll
        for (int q = 0; q < 4; ++q) acc2[p][q] = 0ull;

    for (int kb = 0; kb < CC; kb += 16) {
#pragma unroll
        for (int i = 0; i < 2; ++i) {
            int e4 = tid * 2 + i;
            int oc = e4 >> 2, k4 = (e4 & 3) << 2;
            float4 v = *(const float4*)&W[oc * CC + kb + k4];
            Ws[k4 + 0][oc] = v.x; Ws[k4 + 1][oc] = v.y;
            Ws[k4 + 2][oc] = v.z; Ws[k4 + 3][oc] = v.w;
        }
        __syncthreads();
#pragma unroll
        for (int kk = 0; kk < 16; ++kk) {
            float4 xv = *(const float4*)&Xs[kb + kk][tx * 4];
            ull dx[4];
            dx[0] = dup2(xv.x); dx[1] = dup2(xv.y);
            dx[2] = dup2(xv.z); dx[3] = dup2(xv.w);
            ull wp[4];
#pragma unroll
            for (int p = 0; p < 4; ++p)
                wp[p] = *(const ull*)&Ws[kk][ty * 8 + 2 * p];
#pragma unroll
            for (int p = 0; p < 4; ++p)
#pragma unroll
                for (int q = 0; q < 4; ++q)
                    acc2[p][q] = ffma2(wp[p], dx[q], acc2[p][q]);
        }
        __syncthreads();
    }
#pragma unroll
    for (int p = 0; p < 4; ++p) {
        int oc0 = ty * 8 + 2 * p, oc1 = oc0 + 1;
        float2 u0 = unpk2(acc2[p][0]), u1 = unpk2(acc2[p][1]);
        float2 u2 = unpk2(acc2[p][2]), u3 = unpk2(acc2[p][3]);
        size_t i0 = (size_t)(b * CC + oc0) * TF + p0 + tx * 4;
        size_t i1 = (size_t)(b * CC + oc1) * TF + p0 + tx * 4;
        float bv0 = bias[oc0], bv1 = bias[oc1];
        float4 s0 = *(const float4*)&skip[i0];
        float4 s1 = *(const float4*)&skip[i1];
        float4 o0, o1;
        o0.x = u0.x + bv0 + s0.x; o0.y = u1.x + bv0 + s0.y;
        o0.z = u2.x + bv0 + s0.z; o0.w = u3.x + bv0 + s0.w;
        o1.x = u0.y + bv1 + s1.x; o1.y = u1.y + bv1 + s1.y;
        o1.z = u2.y + bv1 + s1.z; o1.w = u3.y + bv1 + s1.w;
        *(float4*)&out[i0] = o0;
        *(float4*)&out[i1] = o1;
    }
}

// ---------------- weight transpose for convt: (oc,ic,tap) -> [tap][ic][oc] ----
__global__ __launch_bounds__(256) void k_wtT(const float* __restrict__ src)
{
    int i = blockIdx.x * 256 + threadIdx.x;
    if (i < 3 * CC * CC) {
        int oc = i & 127, ic = (i >> 7) & 127, tap = i >> 14;
        g_wtT[i] = src[(oc * CC + ic) * 3 + tap];
    }
}

// ---------------- transposed conv over freq (k=3,s=2) + ReLU, f32x2 ----------
__global__ __launch_bounds__(128) void k_convt(float* __restrict__ out,
                                               const float* __restrict__ in,
                                               const float* __restrict__ bias,
                                               int Fin, int TF)
{
    __shared__ __align__(16) float Xs[128][36];
    __shared__ __align__(16) float Ws[3][16][128];
    int tid = threadIdx.x;
    int tx = tid & 7, ty = tid >> 3;
    int b = blockIdx.y;
    int p0 = blockIdx.x * 32;

#pragma unroll
    for (int i = 0; i < 8; ++i) {
        int e4 = tid + i * 128;
        int ch = e4 >> 3, pq = (e4 & 7) << 2;
        *(float4*)&Xs[ch][pq] = *(const float4*)&in[(size_t)(b * CC + ch) * TF + p0 + pq];
    }
    int p_ = tx * 4;
    bool sh[4];
#pragma unroll
    for (int jj = 0; jj < 4; ++jj) sh[jj] = (((p_ + jj) & (Fin - 1)) != Fin - 1);

    ull ae2[4][4], ao2[4][4];
#pragma unroll
    for (int p = 0; p < 4; ++p)
#pragma unroll
        for (int q = 0; q < 4; ++q) { ae2[p][q] = 0ull; ao2[p][q] = 0ull; }

    for (int kb = 0; kb < CC; kb += 16) {
        __syncthreads();
#pragma unroll
        for (int i = 0; i < 12; ++i) {
            int idx = tid + i * 128;
            int tap = idx / 512, rem = idx & 511;
            int kkk = rem >> 5, oc4 = (rem & 31) << 2;
            *(float4*)&Ws[tap][kkk][oc4] =
                *(const float4*)&g_wtT[(tap * CC + kb + kkk) * CC + oc4];
        }
        __syncthreads();
#pragma unroll
        for (int kk = 0; kk < 16; ++kk) {
            const float* xrow = &Xs[kb + kk][0];
            float4 xv = *(const float4*)&xrow[p_];
            float xnext = xrow[p_ + 4];
            ull dx[4], dxs[4];
            dx[0] = dup2(xv.x); dx[1] = dup2(xv.y);
            dx[2] = dup2(xv.z); dx[3] = dup2(xv.w);
            dxs[0] = dup2(sh[0] ? xv.y : 0.f);
            dxs[1] = dup2(sh[1] ? xv.z : 0.f);
            dxs[2] = dup2(sh[2] ? xv.w : 0.f);
            dxs[3] = dup2(sh[3] ? xnext : 0.f);
            ull w0p[4], w1p[4], w2p[4];
#pragma unroll
            for (int p = 0; p < 4; ++p) {
                w0p[p] = *(const ull*)&Ws[0][kk][ty * 8 + 2 * p];
                w1p[p] = *(const ull*)&Ws[1][kk][ty * 8 + 2 * p];
                w2p[p] = *(const ull*)&Ws[2][kk][ty * 8 + 2 * p];
            }
#pragma unroll
            for (int p = 0; p < 4; ++p)
#pragma unroll
                for (int q = 0; q < 4; ++q) {
                    ae2[p][q] = ffma2(w1p[p], dx[q], ae2[p][q]);
                    ao2[p][q] = ffma2(w0p[p], dx[q], ao2[p][q]);
                    ao2[p][q] = ffma2(w2p[p], dxs[q], ao2[p][q]);
                }
        }
    }
    int TF2 = TF * 2;
#pragma unroll
    for (int p = 0; p < 4; ++p) {
        int oc0 = ty * 8 + 2 * p, oc1 = oc0 + 1;
        float bv0 = bias[oc0], bv1 = bias[oc1];
#pragma unroll
        for (int q = 0; q < 4; ++q) {
            int pp = p0 + p_ + q;
            float2 e = unpk2(ae2[p][q]);
            float2 o = unpk2(ao2[p][q]);
            float2 r0, r1;
            r0.x = fmaxf(e.x + bv0, 0.f); r0.y = fmaxf(o.x + bv0, 0.f);
            r1.x = fmaxf(e.y + bv1, 0.f); r1.y = fmaxf(o.y + bv1, 0.f);
            *(float2*)&out[(size_t)(b * CC + oc0) * TF2 + 2 * pp] = r0;
            *(float2*)&out[(size_t)(b * CC + oc1) * TF2 + 2 * pp] = r1;
        }
    }
}

// ---------------- final: pre = w0p@e0 + b0p + e1x ; m = sigmoid(conv3(pre)) ----
__global__ __launch_bounds__(256) void k_final(const float* __restrict__ e0,
                                               const float* __restrict__ W,
                                               const float* __restrict__ bias,
                                               const float* __restrict__ w0o,
                                               const float* __restrict__ b0o,
                                               float* __restrict__ outm)
{
    __shared__ __align__(16) float Xs[128][64];
    __shared__ __align__(16) float Ws[16][128];
    __shared__ float wo[128][3];
    const int TF = TT * 64;
    int tid = threadIdx.x;
    int tx = tid & 15, ty = tid >> 4;
    int b = blockIdx.y, t = blockIdx.x;
    int p0 = t * 64;

#pragma unroll
    for (int i = 0; i < 8; ++i) {
        int e4 = tid + i * 256;
        int ch = e4 >> 4, pq = (e4 & 15) << 2;
        *(float4*)&Xs[ch][pq] = *(const float4*)&e0[(size_t)(b * CC + ch) * TF + p0 + pq];
    }
    for (int i = tid; i < 384; i += 256) wo[i / 3][i % 3] = w0o[i];

    ull acc2[4][4];
#pragma unroll
    for (int p = 0; p < 4; ++p)
#pragma unroll
        for (int q = 0; q < 4; ++q) acc2[p][q] = 0ull;

    for (int kb = 0; kb < CC; kb += 16) {
#pragma unroll
        for (int i = 0; i < 2; ++i) {
            int e4 = tid * 2 + i;
            int oc = e4 >> 2, k4 = (e4 & 3) << 2;
            float4 v = *(const float4*)&W[oc * CC + kb + k4];
            Ws[k4 + 0][oc] = v.x; Ws[k4 + 1][oc] = v.y;
            Ws[k4 + 2][oc] = v.z; Ws[k4 + 3][oc] = v.w;
        }
        __syncthreads();
#pragma unroll
        for (int kk = 0; kk < 16; ++kk) {
            float4 xv = *(const float4*)&Xs[kb + kk][tx * 4];
            ull dx[4];
            dx[0] = dup2(xv.x); dx[1] = dup2(xv.y);
            dx[2] = dup2(xv.z); dx[3] = dup2(xv.w);
            ull wp[4];
#pragma unroll
            for (int p = 0; p < 4; ++p)
                wp[p] = *(const ull*)&Ws[kk][ty * 8 + 2 * p];
#pragma unroll
            for (int p = 0; p < 4; ++p)
#pragma unroll
                for (int q = 0; q < 4; ++q)
                    acc2[p][q] = ffma2(wp[p], dx[q], acc2[p][q]);
        }
        __syncthreads();
    }
#pragma unroll
    for (int p = 0; p < 4; ++p) {
        int oc0 = ty * 8 + 2 * p, oc1 = oc0 + 1;
        float bv0 = bias[oc0], bv1 = bias[oc1];
        float2 u0 = unpk2(acc2[p][0]), u1 = unpk2(acc2[p][1]);
        float2 u2 = unpk2(acc2[p][2]), u3 = unpk2(acc2[p][3]);
        int pq = tx * 4;
        Xs[oc0][pq + 0] = u0.x + bv0 + g_e1x[(size_t)(b * CC + oc0) * TF + p0 + pq + 0];
        Xs[oc0][pq + 1] = u1.x + bv0 + g_e1x[(size_t)(b * CC + oc0) * TF + p0 + pq + 1];
        Xs[oc0][pq + 2] = u2.x + bv0 + g_e1x[(size_t)(b * CC + oc0) * TF + p0 + pq + 2];
        Xs[oc0][pq + 3] = u3.x + bv0 + g_e1x[(size_t)(b * CC + oc0) * TF + p0 + pq + 3];
        Xs[oc1][pq + 0] = u0.y + bv1 + g_e1x[(size_t)(b * CC + oc1) * TF + p0 + pq + 0];
        Xs[oc1][pq + 1] = u1.y + bv1 + g_e1x[(size_t)(b * CC + oc1) * TF + p0 + pq + 1];
        Xs[oc1][pq + 2] = u2.y + bv1 + g_e1x[(size_t)(b * CC + oc1) * TF + p0 + pq + 2];
        Xs[oc1][pq + 3] = u3.y + bv1 + g_e1x[(size_t)(b * CC + oc1) * TF + p0 + pq + 3];
    }
    __syncthreads();
    int f = tid >> 2, q = tid & 3;
    float s = 0.f;
#pragma unroll 4
    for (int i = 0; i < 32; ++i) {
        int ch = q * 32 + i;
        float x0 = Xs[ch][f];
        float xm = (f > 0) ? Xs[ch][f - 1] : 0.f;
        float xp = (f < 63) ? Xs[ch][f + 1] : 0.f;
        s = fmaf(wo[ch][0], xm, s);
        s = fmaf(wo[ch][1], x0, s);
        s = fmaf(wo[ch][2], xp, s);
    }
    s += __shfl_down_sync(0xffffffffu, s, 1);
    s += __shfl_down_sync(0xffffffffu, s, 2);
    if (q == 0) outm[((size_t)b * TT + t) * 64 + f] = 1.f / (1.f + __expf(-(s + b0o[0])));
}

// ---------------------------------- launch ----------------------------------
extern "C" void kernel_launch(void* const* d_in, const int* in_sizes, int n_in,
                              void* d_out, int out_size)
{
    const float* emb   = (const float*)d_in[0];
    const float* e3    = (const float*)d_in[1];
    const float* e2    = (const float*)d_in[2];
    const float* e1    = (const float*)d_in[3];
    const float* e0    = (const float*)d_in[4];
    const float* h_erb = (const float*)d_in[5];
    const float* Wih   = (const float*)d_in[6];
    const float* Whh   = (const float*)d_in[7];
    const float* bih   = (const float*)d_in[8];
    const float* bhh   = (const float*)d_in[9];
    const float* w3p   = (const float*)d_in[10];
    const float* b3p   = (const float*)d_in[11];
    const float* w2p   = (const float*)d_in[12];
    const float* b2p   = (const float*)d_in[13];
    const float* w1p   = (const float*)d_in[14];
    const float* b1p   = (const float*)d_in[15];
    const float* w0p   = (const float*)d_in[16];
    const float* b0p   = (const float*)d_in[17];
    const float* wt3   = (const float*)d_in[18];
    const float* bt3   = (const float*)d_in[19];
    const float* wt2   = (const float*)d_in[20];
    const float* bt2   = (const float*)d_in[21];
    const float* wt1   = (const float*)d_in[22];
    const float* bt1   = (const float*)d_in[23];
    const float* w0o   = (const float*)d_in[24];
    const float* b0o   = (const float*)d_in[25];
    float* out = (float*)d_out;

    float* gx3;  cudaGetSymbolAddress((void**)&gx3,  g_x3);
    float* ge3x; cudaGetSymbolAddress((void**)&ge3x, g_e3x);
    float* gx2;  cudaGetSymbolAddress((void**)&gx2,  g_x2);
    float* ge2x; cudaGetSymbolAddress((void**)&ge2x, g_e2x);
    float* gx1;  cudaGetSymbolAddress((void**)&gx1,  g_x1);
    float* ge1x; cudaGetSymbolAddress((void**)&ge1x, g_e1x);
    float* gemb2;cudaGetSymbolAddress((void**)&gemb2,g_emb2);

    k_xg<<<dim3(24, 32), 256>>>(emb, Wih, bih);
    k_gru<<<GBLK, 224>>>(h_erb, Whh, bhh, out + BB * TT * 64);

    k_pconv<<<dim3(64, 8),  256>>>(gx3, e3, w3p, b3p, gemb2, TT * 8);
    k_wtT<<<192, 256>>>(wt3);
    k_convt<<<dim3(128, 8), 128>>>(ge3x, gx3, bt3, 8, TT * 8);

    k_pconv<<<dim3(128, 8), 256>>>(gx2, e2, w2p, b2p, ge3x, TT * 16);
    k_wtT<<<192, 256>>>(wt2);
    k_convt<<<dim3(256, 8), 128>>>(ge2x, gx2, bt2, 16, TT * 16);

    k_pconv<<<dim3(256, 8), 256>>>(gx1, e1, w1p, b1p, ge2x, TT * 32);
    k_wtT<<<192, 256>>>(wt1);
    k_convt<<<dim3(512, 8), 128>>>(ge1x, gx1, bt1, 32, TT * 32);

    k_final<<<dim3(512, 8), 256>>>(e0, w0p, b0p, w0o, b0o, out);
}